// round 3
// baseline (speedup 1.0000x reference)
#include <cuda_runtime.h>
#include <cuda_bf16.h>

#define N_TOTAL   16384
#define M_ROWS    4096
#define DIM       256
#define K1_BLOCKS 128
#define ROWS_PER_BLOCK (N_TOTAL / K1_BLOCKS)   // 128

// Scratch (no allocation allowed): per-block column partials, v vector, c scalar.
__device__ float g_part[K1_BLOCKS * DIM];
__device__ float g_v[DIM];
__device__ float g_c;

// ---------------------------------------------------------------------------
// k1: column partial sums of combine_new = [mashup ; new_api]
// 128 blocks x 256 threads. Each block owns 128 rows (entirely inside one
// source tensor: blocks 0..31 -> mashup, 32..127 -> new_api).
// Thread t: sub-row (t>>6), float4-column (t&63). Fully coalesced float4 loads.
// Partials written per block -> deterministic (no float atomics).
// ---------------------------------------------------------------------------
__global__ void colsum_kernel(const float* __restrict__ mashup,
                              const float* __restrict__ new_api) {
    const int t   = threadIdx.x;
    const int sub = t >> 6;     // 0..3
    const int c4  = t & 63;     // float4 column index
    const int row0 = blockIdx.x * ROWS_PER_BLOCK;

    const float* src;
    int base_row;
    if (row0 < M_ROWS) { src = mashup;  base_row = row0; }
    else               { src = new_api; base_row = row0 - M_ROWS; }

    float4 acc = make_float4(0.f, 0.f, 0.f, 0.f);
    #pragma unroll 8
    for (int r = sub; r < ROWS_PER_BLOCK; r += 4) {
        const float4 x = reinterpret_cast<const float4*>(
            src + (size_t)(base_row + r) * DIM)[c4];
        acc.x += x.x; acc.y += x.y; acc.z += x.z; acc.w += x.w;
    }

    __shared__ float4 sm[256];
    sm[t] = acc;
    __syncthreads();
    if (t < 64) {
        float4 a = sm[t], b = sm[t + 64], c = sm[t + 128], d = sm[t + 192];
        float4 r = make_float4(a.x + b.x + c.x + d.x,
                               a.y + b.y + c.y + d.y,
                               a.z + b.z + c.z + d.z,
                               a.w + b.w + c.w + d.w);
        reinterpret_cast<float4*>(g_part + (size_t)blockIdx.x * DIM)[t] = r;
    }
}

// ---------------------------------------------------------------------------
// k2: single block, 1024 threads (32 warps for MLP).
//   s[j]    = sum_b g_part[b][j]
//   ksum[j] = sum_i s[i]*k_w[i][j] + N*k_b[j]
//   c       = sum_j q_b[j]*ksum[j]
//   v[r]    = sum_i q_w[r][i]*ksum[i]       (warp-per-row, coalesced float4)
// ---------------------------------------------------------------------------
__global__ void middle_kernel(const float* __restrict__ q_w,
                              const float* __restrict__ q_b,
                              const float* __restrict__ k_w,
                              const float* __restrict__ k_b) {
    __shared__ float s[DIM];
    __shared__ float ksum[DIM];
    __shared__ float tmp[1024];

    const int t = threadIdx.x;
    const int j = t & 255;       // column
    const int q = t >> 8;        // quarter 0..3

    // --- s: reduce the 128 block-partials, split 32 per quarter ---
    float acc = 0.f;
    #pragma unroll 8
    for (int b = q * 32; b < q * 32 + 32; ++b)
        acc += g_part[b * DIM + j];
    tmp[t] = acc;
    __syncthreads();
    if (t < 256) s[t] = tmp[t] + tmp[t + 256] + tmp[t + 512] + tmp[t + 768];
    __syncthreads();

    // --- ksum: each quarter handles 64 of the 256 i-terms (coalesced in j) ---
    float kk = 0.f;
    #pragma unroll 8
    for (int i = q * 64; i < q * 64 + 64; ++i)
        kk += s[i] * k_w[i * DIM + j];
    tmp[t] = kk;
    __syncthreads();
    if (t < 256)
        ksum[t] = tmp[t] + tmp[t + 256] + tmp[t + 512] + tmp[t + 768]
                + (float)N_TOTAL * k_b[t];
    __syncthreads();

    // --- c = q_b . ksum ---
    if (t < 256) tmp[t] = q_b[t] * ksum[t];
    else         tmp[t] = 0.f;
    __syncthreads();
    for (int off = 128; off > 0; off >>= 1) {
        if (t < off) tmp[t] += tmp[t + off];
        __syncthreads();
    }
    if (t == 0) g_c = tmp[0];

    // --- v: 32 warps, 8 rows each, lanes cover 256 cols as 2 float4s ---
    const int warp = t >> 5, lane = t & 31;
    const float4* kv = reinterpret_cast<const float4*>(ksum);
    const float4  b0 = kv[lane], b1 = kv[lane + 32];
    #pragma unroll
    for (int rr = 0; rr < 8; ++rr) {
        const int row = warp * 8 + rr;
        const float4* qr = reinterpret_cast<const float4*>(q_w + (size_t)row * DIM);
        const float4 a0 = qr[lane], a1 = qr[lane + 32];
        float d = a0.x * b0.x + a0.y * b0.y + a0.z * b0.z + a0.w * b0.w
                + a1.x * b1.x + a1.y * b1.y + a1.z * b1.z + a1.w * b1.w;
        #pragma unroll
        for (int off = 16; off > 0; off >>= 1)
            d += __shfl_xor_sync(0xFFFFFFFFu, d, off);
        if (lane == 0) g_v[row] = d;
    }
}

// ---------------------------------------------------------------------------
// k3: out[i] = (combine[i] . v + c) / 16,  combine = [mashup ; api]
// 2048 blocks x 256 threads = 8 warps/block, one warp per row.
// ---------------------------------------------------------------------------
__global__ void final_kernel(const float* __restrict__ mashup,
                             const float* __restrict__ api,
                             float* __restrict__ out) {
    __shared__ float vs[DIM];
    const int t = threadIdx.x;
    vs[t] = g_v[t];
    __syncthreads();

    const int warp = t >> 5, lane = t & 31;
    const int row = blockIdx.x * 8 + warp;
    const float* src = (row < M_ROWS)
        ? (mashup + (size_t)row * DIM)
        : (api + (size_t)(row - M_ROWS) * DIM);

    const float4* p  = reinterpret_cast<const float4*>(src);
    const float4* vp = reinterpret_cast<const float4*>(vs);
    const float4 x0 = p[lane],  x1 = p[lane + 32];
    const float4 v0 = vp[lane], v1 = vp[lane + 32];
    float acc = x0.x * v0.x + x0.y * v0.y + x0.z * v0.z + x0.w * v0.w
              + x1.x * v1.x + x1.y * v1.y + x1.z * v1.z + x1.w * v1.w;
    #pragma unroll
    for (int off = 16; off > 0; off >>= 1)
        acc += __shfl_xor_sync(0xFFFFFFFFu, acc, off);
    if (lane == 0)
        out[row] = (acc + g_c) * 0.0625f;   // 1/sqrt(256) = 1/16
}

// ---------------------------------------------------------------------------
// Launch: inputs per metadata order:
//   0 mashup [4096,256], 1 api [12288,256], 2 new_api [12288,256],
//   3 q_w [256,256], 4 q_b [256], 5 k_w [256,256], 6 k_b [256],
//   7 embedding_dim (unused, fixed 256)
// ---------------------------------------------------------------------------
extern "C" void kernel_launch(void* const* d_in, const int* in_sizes, int n_in,
                              void* d_out, int out_size) {
    const float* mashup  = (const float*)d_in[0];
    const float* api     = (const float*)d_in[1];
    const float* new_api = (const float*)d_in[2];
    const float* q_w     = (const float*)d_in[3];
    const float* q_b     = (const float*)d_in[4];
    const float* k_w     = (const float*)d_in[5];
    const float* k_b     = (const float*)d_in[6];
    float* out = (float*)d_out;

    colsum_kernel<<<K1_BLOCKS, 256>>>(mashup, new_api);
    middle_kernel<<<1, 1024>>>(q_w, q_b, k_w, k_b);
    final_kernel<<<N_TOTAL / 8, 256>>>(mashup, api, out);
}

// round 4
// speedup vs baseline: 1.2216x; 1.2216x over previous
#include <cuda_runtime.h>
#include <cuda_bf16.h>

#define N_TOTAL   16384
#define M_ROWS    4096
#define DIM       256
#define K1_BLOCKS 148          // one block per SM, zero idle SMs

// Scratch (no allocation allowed)
__device__ float g_part[K1_BLOCKS * DIM];  // per-block column partials
__device__ float g_ksum[DIM];
__device__ float g_v[DIM];
__device__ float g_c;

// ---------------------------------------------------------------------------
// k1: column partial sums of combine_new = [mashup ; new_api]
// 148 blocks x 1024 threads. Grid-strided rows: block b owns rows
// {b, b+148, b+296, ...}. Thread layout: c4 = t&63 (float4 column),
// sub = t>>6 (0..15). Each thread: up to 7 predicated, independent float4
// loads (front-batched by ptxas -> deep MLP). Fixed-order smem reduction
// of the 16 sub-segments -> deterministic, no atomics.
// ---------------------------------------------------------------------------
__global__ void __launch_bounds__(1024, 1)
colsum_kernel(const float* __restrict__ mashup,
              const float* __restrict__ new_api) {
    const int t   = threadIdx.x;
    const int c4  = t & 63;
    const int sub = t >> 6;                 // 0..15
    const int bid = blockIdx.x;

    float4 acc = make_float4(0.f, 0.f, 0.f, 0.f);
    #pragma unroll
    for (int m = 0; m < 7; ++m) {
        const int k = sub + 16 * m;         // 0..111
        const int r = bid + K1_BLOCKS * k;  // global row
        if (r < N_TOTAL) {
            const float* src = (r < M_ROWS)
                ? (mashup + (size_t)r * DIM)
                : (new_api + (size_t)(r - M_ROWS) * DIM);
            const float4 x = reinterpret_cast<const float4*>(src)[c4];
            acc.x += x.x; acc.y += x.y; acc.z += x.z; acc.w += x.w;
        }
    }

    __shared__ float4 sm[1024];
    sm[t] = acc;
    __syncthreads();
    if (t < 64) {
        float4 r = sm[t];
        #pragma unroll
        for (int s = 1; s < 16; ++s) {
            const float4 a = sm[t + 64 * s];
            r.x += a.x; r.y += a.y; r.z += a.z; r.w += a.w;
        }
        reinterpret_cast<float4*>(g_part + (size_t)bid * DIM)[t] = r;
    }
}

// ---------------------------------------------------------------------------
// k2a: 64 blocks x 256 threads.
// Every block re-reduces the (L2-hot) 148 partials into s[256], then
// computes its own 4 columns of ksum[j] = sum_i s[i]*k_w[i][j] + N*k_b[j].
// ---------------------------------------------------------------------------
__global__ void __launch_bounds__(256, 1)
ksum_kernel(const float* __restrict__ k_w,
            const float* __restrict__ k_b) {
    __shared__ float4 red[256];
    __shared__ float  s[DIM];

    const int t   = threadIdx.x;
    const int c4  = t & 63;
    const int seg = t >> 6;                 // 0..3

    // --- s: reduce 148 partial rows, 37 per segment (148 = 4*37) ---
    float4 acc = make_float4(0.f, 0.f, 0.f, 0.f);
    #pragma unroll 8
    for (int p = seg; p < K1_BLOCKS; p += 4) {
        const float4 x = reinterpret_cast<const float4*>(
            g_part + (size_t)p * DIM)[c4];
        acc.x += x.x; acc.y += x.y; acc.z += x.z; acc.w += x.w;
    }
    red[t] = acc;
    __syncthreads();
    if (t < 64) {
        const float4 a = red[t], b = red[t + 64],
                     c = red[t + 128], d = red[t + 192];
        reinterpret_cast<float4*>(s)[t] = make_float4(
            a.x + b.x + c.x + d.x, a.y + b.y + c.y + d.y,
            a.z + b.z + c.z + d.z, a.w + b.w + c.w + d.w);
    }
    __syncthreads();

    // --- ksum for this block's 4 columns: jb = 4*blockIdx.x ---
    const int jb = blockIdx.x * 4;
    const float si = s[t];
    const float4 w = reinterpret_cast<const float4*>(
        k_w + (size_t)t * DIM + jb)[0];
    red[t] = make_float4(si * w.x, si * w.y, si * w.z, si * w.w);
    __syncthreads();
    #pragma unroll
    for (int off = 128; off >= 1; off >>= 1) {
        if (t < off) {
            const float4 a = red[t], b = red[t + off];
            red[t] = make_float4(a.x + b.x, a.y + b.y, a.z + b.z, a.w + b.w);
        }
        __syncthreads();
    }
    if (t == 0) {
        const float4 kb = reinterpret_cast<const float4*>(k_b + jb)[0];
        float4 r = red[0];
        r.x += (float)N_TOTAL * kb.x;
        r.y += (float)N_TOTAL * kb.y;
        r.z += (float)N_TOTAL * kb.z;
        r.w += (float)N_TOTAL * kb.w;
        reinterpret_cast<float4*>(g_ksum + jb)[0] = r;
    }
}

// ---------------------------------------------------------------------------
// k2b: 64 blocks x 256 threads. Block b computes v rows 4b..4b+3
// (v = q_w @ ksum). Block 0 also computes c = q_b . ksum.
// ---------------------------------------------------------------------------
__global__ void __launch_bounds__(256, 1)
vrow_kernel(const float* __restrict__ q_w,
            const float* __restrict__ q_b) {
    __shared__ float ks[DIM];
    __shared__ float red[256];

    const int t = threadIdx.x;
    ks[t] = g_ksum[t];
    __syncthreads();

    const int row = blockIdx.x * 4 + (t >> 6);
    const int i4  = t & 63;
    const float4 a = reinterpret_cast<const float4*>(
        q_w + (size_t)row * DIM)[i4];
    const float4 k = reinterpret_cast<const float4*>(ks)[i4];
    red[t] = a.x * k.x + a.y * k.y + a.z * k.z + a.w * k.w;
    __syncthreads();
    #pragma unroll
    for (int off = 32; off >= 1; off >>= 1) {
        if ((t & 63) < off) red[t] += red[t + off];
        __syncthreads();
    }
    if ((t & 63) == 0) g_v[row] = red[t];

    if (blockIdx.x == 0) {
        __syncthreads();
        red[t] = q_b[t] * ks[t];
        __syncthreads();
        #pragma unroll
        for (int off = 128; off >= 1; off >>= 1) {
            if (t < off) red[t] += red[t + off];
            __syncthreads();
        }
        if (t == 0) g_c = red[0];
    }
}

// ---------------------------------------------------------------------------
// k3: out[i] = (combine[i] . v + c) / 16,  combine = [mashup ; api]
// 512 blocks x 256 threads. Each warp owns 4 rows -> 8 independent float4
// loads per thread (deep MLP), then 4 butterfly reductions.
// ---------------------------------------------------------------------------
__global__ void __launch_bounds__(256, 4)
final_kernel(const float* __restrict__ mashup,
             const float* __restrict__ api,
             float* __restrict__ out) {
    __shared__ float vs[DIM];
    __shared__ float sc;
    const int t = threadIdx.x;
    vs[t] = g_v[t];
    if (t == 0) sc = g_c;
    __syncthreads();

    const int warp = t >> 5, lane = t & 31;
    const int row0 = (blockIdx.x * 8 + warp) * 4;   // 4 rows per warp

    const float* src;
    int base;
    if (row0 < M_ROWS) { src = mashup; base = row0; }
    else               { src = api;    base = row0 - M_ROWS; }

    const float4* vp = reinterpret_cast<const float4*>(vs);
    const float4 v0 = vp[lane], v1 = vp[lane + 32];

    float acc[4];
    #pragma unroll
    for (int r = 0; r < 4; ++r) {
        const float4* p = reinterpret_cast<const float4*>(
            src + (size_t)(base + r) * DIM);
        const float4 x0 = p[lane], x1 = p[lane + 32];
        acc[r] = x0.x * v0.x + x0.y * v0.y + x0.z * v0.z + x0.w * v0.w
               + x1.x * v1.x + x1.y * v1.y + x1.z * v1.z + x1.w * v1.w;
    }
    #pragma unroll
    for (int r = 0; r < 4; ++r) {
        float a = acc[r];
        #pragma unroll
        for (int off = 16; off > 0; off >>= 1)
            a += __shfl_xor_sync(0xFFFFFFFFu, a, off);
        if (lane == 0)
            out[row0 + r] = (a + sc) * 0.0625f;    // 1/sqrt(256)
    }
}

// ---------------------------------------------------------------------------
// Launch. Inputs (metadata order): mashup, api, new_api, q_w, q_b, k_w, k_b,
// embedding_dim (fixed 256, unused).
// ---------------------------------------------------------------------------
extern "C" void kernel_launch(void* const* d_in, const int* in_sizes, int n_in,
                              void* d_out, int out_size) {
    const float* mashup  = (const float*)d_in[0];
    const float* api     = (const float*)d_in[1];
    const float* new_api = (const float*)d_in[2];
    const float* q_w     = (const float*)d_in[3];
    const float* q_b     = (const float*)d_in[4];
    const float* k_w     = (const float*)d_in[5];
    const float* k_b     = (const float*)d_in[6];
    float* out = (float*)d_out;

    colsum_kernel<<<K1_BLOCKS, 1024>>>(mashup, new_api);
    ksum_kernel<<<DIM / 4, 256>>>(k_w, k_b);
    vrow_kernel<<<DIM / 4, 256>>>(q_w, q_b);
    final_kernel<<<N_TOTAL / 32, 256>>>(mashup, api, out);
}

// round 5
// speedup vs baseline: 1.2359x; 1.0117x over previous
#include <cuda_runtime.h>
#include <cuda_bf16.h>

#define N_TOTAL   16384
#define M_ROWS    4096
#define DIM       256
#define K1_BLOCKS 148          // one block per SM, zero idle SMs

// Scratch (no allocation allowed)
__device__ float g_part[K1_BLOCKS * DIM];  // per-block column partials
__device__ float g_ksum[DIM];
__device__ float g_v[DIM];
__device__ float g_c;

// ---------------------------------------------------------------------------
// k1: column partial sums of combine_new = [mashup ; new_api]
// 148 blocks x 1024 threads. Grid-strided rows: block b owns rows
// {b, b+148, b+296, ...}. Thread layout: c4 = t&63 (float4 column),
// sub = t>>6 (0..15). Each thread: up to 7 predicated, independent float4
// loads (front-batched by ptxas -> deep MLP). Fixed-order smem reduction
// of the 16 sub-segments -> deterministic, no atomics.
// ---------------------------------------------------------------------------
__global__ void __launch_bounds__(1024, 1)
colsum_kernel(const float* __restrict__ mashup,
              const float* __restrict__ new_api) {
    const int t   = threadIdx.x;
    const int c4  = t & 63;
    const int sub = t >> 6;                 // 0..15
    const int bid = blockIdx.x;

    float4 acc = make_float4(0.f, 0.f, 0.f, 0.f);
    #pragma unroll
    for (int m = 0; m < 7; ++m) {
        const int k = sub + 16 * m;         // 0..111
        const int r = bid + K1_BLOCKS * k;  // global row
        if (r < N_TOTAL) {
            const float* src = (r < M_ROWS)
                ? (mashup + (size_t)r * DIM)
                : (new_api + (size_t)(r - M_ROWS) * DIM);
            const float4 x = reinterpret_cast<const float4*>(src)[c4];
            acc.x += x.x; acc.y += x.y; acc.z += x.z; acc.w += x.w;
        }
    }

    __shared__ float4 sm[1024];
    sm[t] = acc;
    __syncthreads();
    if (t < 64) {
        float4 r = sm[t];
        #pragma unroll
        for (int s = 1; s < 16; ++s) {
            const float4 a = sm[t + 64 * s];
            r.x += a.x; r.y += a.y; r.z += a.z; r.w += a.w;
        }
        reinterpret_cast<float4*>(g_part + (size_t)bid * DIM)[t] = r;
    }
}

// ---------------------------------------------------------------------------
// k2a: 64 blocks x 256 threads.
// Every block re-reduces the (L2-hot) 148 partials into s[256], then
// computes its own 4 columns of ksum[j] = sum_i s[i]*k_w[i][j] + N*k_b[j].
// ---------------------------------------------------------------------------
__global__ void __launch_bounds__(256, 1)
ksum_kernel(const float* __restrict__ k_w,
            const float* __restrict__ k_b) {
    __shared__ float4 red[256];
    __shared__ float  s[DIM];

    const int t   = threadIdx.x;
    const int c4  = t & 63;
    const int seg = t >> 6;                 // 0..3

    // --- s: reduce 148 partial rows, 37 per segment (148 = 4*37) ---
    float4 acc = make_float4(0.f, 0.f, 0.f, 0.f);
    #pragma unroll 8
    for (int p = seg; p < K1_BLOCKS; p += 4) {
        const float4 x = reinterpret_cast<const float4*>(
            g_part + (size_t)p * DIM)[c4];
        acc.x += x.x; acc.y += x.y; acc.z += x.z; acc.w += x.w;
    }
    red[t] = acc;
    __syncthreads();
    if (t < 64) {
        const float4 a = red[t], b = red[t + 64],
                     c = red[t + 128], d = red[t + 192];
        reinterpret_cast<float4*>(s)[t] = make_float4(
            a.x + b.x + c.x + d.x, a.y + b.y + c.y + d.y,
            a.z + b.z + c.z + d.z, a.w + b.w + c.w + d.w);
    }
    __syncthreads();

    // --- ksum for this block's 4 columns: jb = 4*blockIdx.x ---
    const int jb = blockIdx.x * 4;
    const float si = s[t];
    const float4 w = reinterpret_cast<const float4*>(
        k_w + (size_t)t * DIM + jb)[0];
    red[t] = make_float4(si * w.x, si * w.y, si * w.z, si * w.w);
    __syncthreads();
    #pragma unroll
    for (int off = 128; off >= 1; off >>= 1) {
        if (t < off) {
            const float4 a = red[t], b = red[t + off];
            red[t] = make_float4(a.x + b.x, a.y + b.y, a.z + b.z, a.w + b.w);
        }
        __syncthreads();
    }
    if (t == 0) {
        const float4 kb = reinterpret_cast<const float4*>(k_b + jb)[0];
        float4 r = red[0];
        r.x += (float)N_TOTAL * kb.x;
        r.y += (float)N_TOTAL * kb.y;
        r.z += (float)N_TOTAL * kb.z;
        r.w += (float)N_TOTAL * kb.w;
        reinterpret_cast<float4*>(g_ksum + jb)[0] = r;
    }
}

// ---------------------------------------------------------------------------
// k2b: 64 blocks x 256 threads. Block b computes v rows 4b..4b+3
// (v = q_w @ ksum). Block 0 also computes c = q_b . ksum.
// ---------------------------------------------------------------------------
__global__ void __launch_bounds__(256, 1)
vrow_kernel(const float* __restrict__ q_w,
            const float* __restrict__ q_b) {
    __shared__ float ks[DIM];
    __shared__ float red[256];

    const int t = threadIdx.x;
    ks[t] = g_ksum[t];
    __syncthreads();

    const int row = blockIdx.x * 4 + (t >> 6);
    const int i4  = t & 63;
    const float4 a = reinterpret_cast<const float4*>(
        q_w + (size_t)row * DIM)[i4];
    const float4 k = reinterpret_cast<const float4*>(ks)[i4];
    red[t] = a.x * k.x + a.y * k.y + a.z * k.z + a.w * k.w;
    __syncthreads();
    #pragma unroll
    for (int off = 32; off >= 1; off >>= 1) {
        if ((t & 63) < off) red[t] += red[t + off];
        __syncthreads();
    }
    if ((t & 63) == 0) g_v[row] = red[t];

    if (blockIdx.x == 0) {
        __syncthreads();
        red[t] = q_b[t] * ks[t];
        __syncthreads();
        #pragma unroll
        for (int off = 128; off >= 1; off >>= 1) {
            if (t < off) red[t] += red[t + off];
            __syncthreads();
        }
        if (t == 0) g_c = red[0];
    }
}

// ---------------------------------------------------------------------------
// k3: out[i] = (combine[i] . v + c) / 16,  combine = [mashup ; api]
// 512 blocks x 256 threads. Each warp owns 4 rows -> 8 independent float4
// loads per thread (deep MLP), then 4 butterfly reductions.
// ---------------------------------------------------------------------------
__global__ void __launch_bounds__(256, 4)
final_kernel(const float* __restrict__ mashup,
             const float* __restrict__ api,
             float* __restrict__ out) {
    __shared__ float vs[DIM];
    __shared__ float sc;
    const int t = threadIdx.x;
    vs[t] = g_v[t];
    if (t == 0) sc = g_c;
    __syncthreads();

    const int warp = t >> 5, lane = t & 31;
    const int row0 = (blockIdx.x * 8 + warp) * 4;   // 4 rows per warp

    const float* src;
    int base;
    if (row0 < M_ROWS) { src = mashup; base = row0; }
    else               { src = api;    base = row0 - M_ROWS; }

    const float4* vp = reinterpret_cast<const float4*>(vs);
    const float4 v0 = vp[lane], v1 = vp[lane + 32];

    float acc[4];
    #pragma unroll
    for (int r = 0; r < 4; ++r) {
        const float4* p = reinterpret_cast<const float4*>(
            src + (size_t)(base + r) * DIM);
        const float4 x0 = p[lane], x1 = p[lane + 32];
        acc[r] = x0.x * v0.x + x0.y * v0.y + x0.z * v0.z + x0.w * v0.w
               + x1.x * v1.x + x1.y * v1.y + x1.z * v1.z + x1.w * v1.w;
    }
    #pragma unroll
    for (int r = 0; r < 4; ++r) {
        float a = acc[r];
        #pragma unroll
        for (int off = 16; off > 0; off >>= 1)
            a += __shfl_xor_sync(0xFFFFFFFFu, a, off);
        if (lane == 0)
            out[row0 + r] = (a + sc) * 0.0625f;    // 1/sqrt(256)
    }
}

// ---------------------------------------------------------------------------
// Launch. Inputs (metadata order): mashup, api, new_api, q_w, q_b, k_w, k_b,
// embedding_dim (fixed 256, unused).
// ---------------------------------------------------------------------------
extern "C" void kernel_launch(void* const* d_in, const int* in_sizes, int n_in,
                              void* d_out, int out_size) {
    const float* mashup  = (const float*)d_in[0];
    const float* api     = (const float*)d_in[1];
    const float* new_api = (const float*)d_in[2];
    const float* q_w     = (const float*)d_in[3];
    const float* q_b     = (const float*)d_in[4];
    const float* k_w     = (const float*)d_in[5];
    const float* k_b     = (const float*)d_in[6];
    float* out = (float*)d_out;

    colsum_kernel<<<K1_BLOCKS, 1024>>>(mashup, new_api);
    ksum_kernel<<<DIM / 4, 256>>>(k_w, k_b);
    vrow_kernel<<<DIM / 4, 256>>>(q_w, q_b);
    final_kernel<<<N_TOTAL / 32, 256>>>(mashup, api, out);
}